// round 16
// baseline (speedup 1.0000x reference)
#include <cuda_runtime.h>
#include <cuda_bf16.h>
#include <cuda_fp16.h>
#include <cstdint>

// Problem constants
#define BB    2
#define HW    4096
#define NTGT  4096
#define CC    512
#define HH    8
#define KNN   32
#define DH    64
#define MROWS (BB * HW)      // 8192
#define SCALE 0.125f
#define NCHUNK 4
#define CHROWS (MROWS / NCHUNK)   // 2048

// ---------------- scratch (device globals: allocation-free) ----------------
__device__ __half g_qh[(size_t)MROWS * CC];
__device__ __half g_kh[(size_t)MROWS * CC];
__device__ __half g_vh[(size_t)MROWS * CC];
__device__ __half g_Sh[(size_t)MROWS * CC];    // src fp16
__device__ __half g_Th[(size_t)MROWS * CC];    // tgt fp16
__device__ __half g_Oh[(size_t)MROWS * CC];    // attn-out fp16
__device__ __half g_Wt[4][CC * CC];            // [N][K] fp16

// ---------------- helpers ----------------------------------------------------
__device__ __forceinline__ uint32_t smem_to_u32(const void* p) {
    uint32_t a;
    asm("{ .reg .u64 t; cvta.to.shared.u64 t, %1; cvt.u32.u64 %0, t; }"
        : "=r"(a) : "l"(p));
    return a;
}
__device__ __forceinline__ void cp16(uint32_t dst, const void* src) {
    asm volatile("cp.async.cg.shared.global [%0], [%1], 16;" :: "r"(dst), "l"(src));
}
#define CP_COMMIT() asm volatile("cp.async.commit_group;" ::: "memory")
#define CP_WAIT(n)  asm volatile("cp.async.wait_group %0;" :: "n"(n) : "memory")

__device__ __forceinline__ uint32_t pack2h(__half a, __half b) {
    __half2 t = __halves2half2(a, b);
    return *reinterpret_cast<uint32_t*>(&t);
}

#define MMA_F16(d, a0, a1, a2, a3, b0, b1) \
    asm volatile( \
        "mma.sync.aligned.m16n8k16.row.col.f32.f16.f16.f32 " \
        "{%0,%1,%2,%3}, {%4,%5,%6,%7}, {%8,%9}, {%0,%1,%2,%3};" \
        : "+f"((d)[0]), "+f"((d)[1]), "+f"((d)[2]), "+f"((d)[3]) \
        : "r"(a0), "r"(a1), "r"(a2), "r"(a3), "r"(b0), "r"(b1))

// ---------------- fused prep: weight transpose (4x) + src/tgt fp16 convert --
__global__ void __launch_bounds__(256) prep_kernel(
    const float* __restrict__ W0, const float* __restrict__ W1,
    const float* __restrict__ W2, const float* __restrict__ W3,
    __half* __restrict__ wt,
    const float* __restrict__ S, const float* __restrict__ T,
    __half* __restrict__ sh, __half* __restrict__ th)
{
    const int bid = blockIdx.x;
    const int tid = threadIdx.x;
    if (bid < 1024) {
        __shared__ float t[32][33];
        const int w   = bid >> 8;
        const int rem = bid & 255;
        const int kt  = (rem & 15) * 32;
        const int nt  = (rem >> 4) * 32;
        const float* W = (w == 0) ? W0 : (w == 1) ? W1 : (w == 2) ? W2 : W3;
        const size_t wo = (size_t)w * CC * CC;
        const int tx = tid & 31, ty = tid >> 5;   // (32, 8)
        #pragma unroll
        for (int i = 0; i < 4; ++i)
            t[ty + i * 8][tx] = W[(size_t)(kt + ty + i * 8) * CC + nt + tx];
        __syncthreads();
        #pragma unroll
        for (int i = 0; i < 4; ++i) {
            float x = t[tx][ty + i * 8];
            wt[wo + (size_t)(nt + ty + i * 8) * CC + kt + tx] = __float2half_rn(x);
        }
    } else {
        const int cb = bid - 1024;                // 0..8191
        const bool is_t = cb >= 4096;
        const float* X = is_t ? T : S;
        __half* o = is_t ? th : sh;
        const int i = (is_t ? cb - 4096 : cb) * 256 + tid;
        const float4 x = reinterpret_cast<const float4*>(X)[i];
        reinterpret_cast<uint2*>(o)[i] =
            make_uint2(pack2h(__float2half_rn(x.x), __float2half_rn(x.y)),
                       pack2h(__float2half_rn(x.z), __float2half_rn(x.w)));
    }
}

// ---------------- fp16 single-term mma GEMM body (3-stage, BK=64) ----------
#define ROWB 144
#define REG_SZ (128 * ROWB)
#define STG_SZ (2 * REG_SZ)
#define OFF_B  REG_SZ
#define SM_TOT (3 * STG_SZ)             // 110592

template <typename OutT>
__device__ __forceinline__ void store2(OutT* p, float a, float b);
template <> __device__ __forceinline__ void store2<float>(float* p, float a, float b) {
    *reinterpret_cast<float2*>(p) = make_float2(a, b);
}
template <> __device__ __forceinline__ void store2<__half>(__half* p, float a, float b) {
    *reinterpret_cast<__half2*>(p) = __floats2half2_rn(a, b);
}

template <typename OutT>
__device__ __forceinline__ void gemm_body(
    uint32_t sb, const __half* __restrict__ A, const __half* __restrict__ Wt,
    const float* __restrict__ bias, OutT* __restrict__ C,
    int bm, int bn)
{
    const int tid  = threadIdx.x;
    const int wid  = tid >> 5;
    const int lane = tid & 31;
    const int wm   = wid & 1;
    const int wn   = wid >> 1;

    const int lr = tid >> 3;
    const int lq = tid & 7;

    float acc[4][4][4];
    #pragma unroll
    for (int a = 0; a < 4; ++a)
        #pragma unroll
        for (int b = 0; b < 4; ++b)
            #pragma unroll
            for (int c = 0; c < 4; ++c) acc[a][b][c] = 0.f;

    auto load_stage = [&](int s, int kt) {
        const int kb = kt * 64;
        const uint32_t base = (uint32_t)(s * STG_SZ);
        #pragma unroll
        for (int i = 0; i < 4; ++i) {
            const int row = i * 32 + lr;
            const uint32_t so = base + (uint32_t)(row * ROWB + lq * 16);
            cp16(sb + so, A + (size_t)(bm + row) * CC + kb + lq * 8);
            cp16(sb + OFF_B + so, Wt + (size_t)(bn + row) * CC + kb + lq * 8);
        }
    };

    load_stage(0, 0);
    CP_COMMIT();
    load_stage(1, 1);
    CP_COMMIT();

    const int sub16 = lane & 15;
    const int ahalf = lane >> 4;
    const int bn8   = lane & 7;
    const int bk16  = (lane >> 3) & 1;

    #pragma unroll 1
    for (int kt = 0; kt < 8; ++kt) {
        const int s = kt % 3;
        if (kt < 7) { CP_WAIT(1); } else { CP_WAIT(0); }
        __syncthreads();
        if (kt + 2 < 8) {
            load_stage((kt + 2) % 3, kt + 2);
            CP_COMMIT();
        }

        const uint32_t aBase = sb + (uint32_t)(s * STG_SZ);
        const uint32_t bBase = aBase + OFF_B;

        #pragma unroll
        for (int s2 = 0; s2 < 4; ++s2) {
            const int kbyte = s2 * 32;

            uint32_t bh[4][2];
            #pragma unroll
            for (int nf = 0; nf < 4; ++nf) {
                const uint32_t brow = (uint32_t)(wn * 32 + nf * 8 + bn8);
                const uint32_t ba = bBase + brow * ROWB + kbyte + bk16 * 16;
                asm volatile(
                    "ldmatrix.sync.aligned.m8n8.x2.shared.b16 {%0,%1}, [%2];"
                    : "=r"(bh[nf][0]), "=r"(bh[nf][1]) : "r"(ba));
            }
            uint32_t ah[4][4];
            #pragma unroll
            for (int mf = 0; mf < 4; ++mf) {
                const uint32_t arow = (uint32_t)(wm * 64 + mf * 16 + sub16);
                const uint32_t aa = aBase + arow * ROWB + kbyte + ahalf * 16;
                asm volatile(
                    "ldmatrix.sync.aligned.m8n8.x4.shared.b16 {%0,%1,%2,%3}, [%4];"
                    : "=r"(ah[mf][0]), "=r"(ah[mf][1]), "=r"(ah[mf][2]), "=r"(ah[mf][3])
                    : "r"(aa));
            }

            #pragma unroll
            for (int mf = 0; mf < 4; ++mf)
                #pragma unroll
                for (int nf = 0; nf < 4; ++nf)
                    MMA_F16(acc[mf][nf], ah[mf][0], ah[mf][1], ah[mf][2], ah[mf][3],
                            bh[nf][0], bh[nf][1]);
        }
    }

    const int g = lane >> 2;
    const int t = lane & 3;
    #pragma unroll
    for (int mf = 0; mf < 4; ++mf) {
        const int row = bm + wm * 64 + mf * 16 + g;
        #pragma unroll
        for (int nf = 0; nf < 4; ++nf) {
            const int col = wn * 32 + nf * 8 + 2 * t;
            const float b0 = __ldg(bias + col);
            const float b1 = __ldg(bias + col + 1);
            float* d = acc[mf][nf];
            store2<OutT>(C + (size_t)row * CC + col, d[0] + b0, d[1] + b1);
            store2<OutT>(C + (size_t)(row + 8) * CC + col, d[2] + b0, d[3] + b1);
        }
    }
}

// single-output GEMM with M offset (used for O projection chunks)
template <typename OutT>
__global__ void __launch_bounds__(256, 2) mma_gemm_bias(
    const __half* __restrict__ A, const __half* __restrict__ Wt,
    const float* __restrict__ bias, OutT* __restrict__ C, int bm0)
{
    extern __shared__ char sm[];
    const uint32_t sb = smem_to_u32(sm);
    const int bm = bm0 + blockIdx.y * 128;
    const int bn = blockIdx.x * 128;
    gemm_body<OutT>(sb, A, Wt, bias + bn, C + bn, bm, bn);
}

// fused Q+K+V GEMM: blockIdx.x in [0,12); w = x>>2 selects projection
__global__ void __launch_bounds__(256, 2) mma_gemm_bias_qkv(
    const __half* __restrict__ Sh, const __half* __restrict__ Th,
    const __half* __restrict__ Wt,
    const float* __restrict__ bq, const float* __restrict__ bk,
    const float* __restrict__ bv,
    __half* __restrict__ Cq, __half* __restrict__ Ck, __half* __restrict__ Cv)
{
    extern __shared__ char sm[];
    const uint32_t sb = smem_to_u32(sm);
    const int bm = blockIdx.y * 128;
    const int w  = blockIdx.x >> 2;       // 0=Q, 1=K, 2=V
    const int bn = (blockIdx.x & 3) * 128;
    const __half* A = (w == 0) ? Sh : Th;
    const __half* W = Wt + (size_t)w * CC * CC;
    const float*  b = (w == 0) ? bq : (w == 1) ? bk : bv;
    __half*       C = (w == 0) ? Cq : (w == 1) ? Ck : Cv;
    gemm_body<__half>(sb, A, W, b + bn, C + bn, bm, bn);
}

// ---------------- gather attention: fp16 Q/K/V, one warp per (b,q) ----------
__global__ void __launch_bounds__(256) attn_kernel(
    const __half* __restrict__ q, const __half* __restrict__ k,
    const __half* __restrict__ v, const int* __restrict__ indices,
    const float* __restrict__ weights, __half* __restrict__ oh, int bq0)
{
    __shared__ float slog[8 * 8 * 33];
    const int wid  = threadIdx.x >> 5;
    const int lane = threadIdx.x & 31;
    const int bq   = bq0 + blockIdx.x * 8 + wid;
    const int b    = bq >> 12;
    float* sl = slog + wid * (8 * 33);

    const __half* kb = k + (size_t)b * NTGT * CC;
    const __half* vb = v + (size_t)b * NTGT * CC;

    const int idxl = indices[(size_t)bq * KNN + lane];

    float qf[2][8];
    {
        const uint4* qrow = reinterpret_cast<const uint4*>(q + (size_t)bq * CC);
        #pragma unroll
        for (int i = 0; i < 2; ++i) {
            const uint4 qq = qrow[i * 32 + lane];
            const __half2* qh2 = reinterpret_cast<const __half2*>(&qq);
            #pragma unroll
            for (int h2 = 0; h2 < 4; ++h2) {
                const float2 f = __half22float2(qh2[h2]);
                qf[i][2 * h2]     = f.x;
                qf[i][2 * h2 + 1] = f.y;
            }
        }
    }

    #pragma unroll 4
    for (int j = 0; j < KNN; ++j) {
        const int ij = __shfl_sync(0xffffffffu, idxl, j);
        const uint4* krow = reinterpret_cast<const uint4*>(kb + (size_t)ij * CC);
        float part[2];
        #pragma unroll
        for (int i = 0; i < 2; ++i) {
            const uint4 kk = krow[i * 32 + lane];
            const __half2* kh = reinterpret_cast<const __half2*>(&kk);
            float p = 0.f;
            #pragma unroll
            for (int h2 = 0; h2 < 4; ++h2) {
                const float2 kf = __half22float2(kh[h2]);
                p = fmaf(qf[i][2 * h2], kf.x, p);
                p = fmaf(qf[i][2 * h2 + 1], kf.y, p);
            }
            part[i] = p;
        }
        #pragma unroll
        for (int off = 4; off >= 1; off >>= 1) {
            part[0] += __shfl_xor_sync(0xffffffffu, part[0], off);
            part[1] += __shfl_xor_sync(0xffffffffu, part[1], off);
        }
        if ((lane & 7) == 0) {
            sl[(0 * 4 + (lane >> 3)) * 33 + j] = part[0];
            sl[(1 * 4 + (lane >> 3)) * 33 + j] = part[1];
        }
    }
    __syncwarp();

    {
        const int h  = lane >> 2;
        const int j0 = lane & 3;
        float vals[8];
        #pragma unroll
        for (int t = 0; t < 8; ++t) {
            const int j = j0 + 4 * t;
            vals[t] = sl[h * 33 + j] * SCALE + weights[(size_t)bq * KNN + j];
        }
        float m = vals[0];
        #pragma unroll
        for (int t = 1; t < 8; ++t) m = fmaxf(m, vals[t]);
        m = fmaxf(m, __shfl_xor_sync(0xffffffffu, m, 1));
        m = fmaxf(m, __shfl_xor_sync(0xffffffffu, m, 2));
        float s = 0.f;
        #pragma unroll
        for (int t = 0; t < 8; ++t) { vals[t] = __expf(vals[t] - m); s += vals[t]; }
        s += __shfl_xor_sync(0xffffffffu, s, 1);
        s += __shfl_xor_sync(0xffffffffu, s, 2);
        const float inv = 1.f / s;
        #pragma unroll
        for (int t = 0; t < 8; ++t) sl[h * 33 + j0 + 4 * t] = vals[t] * inv;
    }
    __syncwarp();

    float acc[2][8];
    #pragma unroll
    for (int i = 0; i < 2; ++i)
        #pragma unroll
        for (int d = 0; d < 8; ++d) acc[i][d] = 0.f;

    const int hsub = lane >> 3;
    #pragma unroll 4
    for (int j = 0; j < KNN; ++j) {
        const int ij = __shfl_sync(0xffffffffu, idxl, j);
        const uint4* vrow = reinterpret_cast<const uint4*>(vb + (size_t)ij * CC);
        #pragma unroll
        for (int i = 0; i < 2; ++i) {
            const float pj = sl[(i * 4 + hsub) * 33 + j];
            const uint4 vv = vrow[i * 32 + lane];
            const __half2* vh = reinterpret_cast<const __half2*>(&vv);
            #pragma unroll
            for (int h2 = 0; h2 < 4; ++h2) {
                const float2 vf = __half22float2(vh[h2]);
                acc[i][2 * h2]     = fmaf(pj, vf.x, acc[i][2 * h2]);
                acc[i][2 * h2 + 1] = fmaf(pj, vf.y, acc[i][2 * h2 + 1]);
            }
        }
    }

    #pragma unroll
    for (int i = 0; i < 2; ++i) {
        const size_t d = (size_t)bq * CC + i * 256 + lane * 8;
        uint32_t hw[4];
        #pragma unroll
        for (int p = 0; p < 4; ++p)
            hw[p] = pack2h(__float2half_rn(acc[i][2 * p]),
                           __float2half_rn(acc[i][2 * p + 1]));
        *reinterpret_cast<uint4*>(oh + d) = make_uint4(hw[0], hw[1], hw[2], hw[3]);
    }
}

// ---------------- launch ----------------------------------------------------
extern "C" void kernel_launch(void* const* d_in, const int* in_sizes, int n_in,
                              void* d_out, int out_size)
{
    const float* src = (const float*)d_in[0];
    const float* tgt = (const float*)d_in[1];
    const int*   idx = (const int*)d_in[2];
    const float* wts = (const float*)d_in[3];
    const float* Wq  = (const float*)d_in[4];
    const float* bq  = (const float*)d_in[5];
    const float* Wk  = (const float*)d_in[6];
    const float* bk  = (const float*)d_in[7];
    const float* Wv  = (const float*)d_in[8];
    const float* bv  = (const float*)d_in[9];
    const float* Wo  = (const float*)d_in[10];
    const float* bo  = (const float*)d_in[11];
    float*       out = (float*)d_out;

    void *pqh, *pkh, *pvh, *psh, *pth, *poh, *pwt;
    cudaGetSymbolAddress(&pqh, g_qh);
    cudaGetSymbolAddress(&pkh, g_kh);
    cudaGetSymbolAddress(&pvh, g_vh);
    cudaGetSymbolAddress(&psh, g_Sh);
    cudaGetSymbolAddress(&pth, g_Th);
    cudaGetSymbolAddress(&poh, g_Oh);
    cudaGetSymbolAddress(&pwt, g_Wt);
    __half* gqh = (__half*)pqh;
    __half* gkh = (__half*)pkh;
    __half* gvh = (__half*)pvh;
    __half* sh  = (__half*)psh;
    __half* th  = (__half*)pth;
    __half* oh  = (__half*)poh;
    __half* wt  = (__half*)pwt;

    static cudaStream_t s1 = nullptr;
    static cudaEvent_t  evA[NCHUNK];
    static cudaEvent_t  evJoin = nullptr;
    static bool init_done = false;
    if (!init_done) {
        cudaFuncSetAttribute(mma_gemm_bias<float>,
                             cudaFuncAttributeMaxDynamicSharedMemorySize, SM_TOT);
        cudaFuncSetAttribute(mma_gemm_bias_qkv,
                             cudaFuncAttributeMaxDynamicSharedMemorySize, SM_TOT);
        cudaStreamCreateWithFlags(&s1, cudaStreamNonBlocking);
        for (int c = 0; c < NCHUNK; ++c)
            cudaEventCreateWithFlags(&evA[c], cudaEventDisableTiming);
        cudaEventCreateWithFlags(&evJoin, cudaEventDisableTiming);
        init_done = true;
    }

    const size_t WS = (size_t)CC * CC;

    // fused prep: 1024 transpose blocks + 8192 convert blocks
    prep_kernel<<<9216, 256>>>(Wq, Wk, Wv, Wo, wt, src, tgt, sh, th);

    dim3 qkvgrid(3 * CC / 128, MROWS / 128);   // (12, 64) = 768 CTAs
    mma_gemm_bias_qkv<<<qkvgrid, 256, SM_TOT>>>(sh, th, wt,
                                                bq, bk, bv, gqh, gkh, gvh);

    // pipelined attn chunks (stream 0) + O-GEMM chunks (stream s1)
    dim3 ogrid(CC / 128, CHROWS / 128);        // (4, 16)
    for (int c = 0; c < NCHUNK; ++c) {
        attn_kernel<<<CHROWS / 8, 256>>>(gqh, gkh, gvh, idx, wts, oh,
                                         c * CHROWS);
        cudaEventRecord(evA[c], 0);
        cudaStreamWaitEvent(s1, evA[c], 0);
        mma_gemm_bias<float><<<ogrid, 256, SM_TOT, s1>>>(
            oh, wt + 3 * WS, bo, out, c * CHROWS);
    }
    // join s1 back into the origin stream
    cudaEventRecord(evJoin, s1);
    cudaStreamWaitEvent(0, evJoin, 0);
}

// round 17
// speedup vs baseline: 1.1737x; 1.1737x over previous
#include <cuda_runtime.h>
#include <cuda_bf16.h>
#include <cuda_fp16.h>
#include <cstdint>

// Problem constants
#define BB    2
#define HW    4096
#define NTGT  4096
#define CC    512
#define HH    8
#define KNN   32
#define DH    64
#define MROWS (BB * HW)      // 8192
#define SCALE 0.125f

// ---------------- scratch (device globals: allocation-free) ----------------
__device__ __half g_qh[(size_t)MROWS * CC];
__device__ __half g_kh[(size_t)MROWS * CC];
__device__ __half g_vh[(size_t)MROWS * CC];
__device__ __half g_Sh[(size_t)MROWS * CC];    // src fp16
__device__ __half g_Th[(size_t)MROWS * CC];    // tgt fp16
__device__ __half g_Oh[(size_t)MROWS * CC];    // attn-out fp16
__device__ __half g_Wt[4][CC * CC];            // [N][K] fp16

// ---------------- helpers ----------------------------------------------------
__device__ __forceinline__ uint32_t smem_to_u32(const void* p) {
    uint32_t a;
    asm("{ .reg .u64 t; cvta.to.shared.u64 t, %1; cvt.u32.u64 %0, t; }"
        : "=r"(a) : "l"(p));
    return a;
}
__device__ __forceinline__ void cp16(uint32_t dst, const void* src) {
    asm volatile("cp.async.cg.shared.global [%0], [%1], 16;" :: "r"(dst), "l"(src));
}
#define CP_COMMIT() asm volatile("cp.async.commit_group;" ::: "memory")
#define CP_WAIT(n)  asm volatile("cp.async.wait_group %0;" :: "n"(n) : "memory")

__device__ __forceinline__ uint32_t pack2h(__half a, __half b) {
    __half2 t = __halves2half2(a, b);
    return *reinterpret_cast<uint32_t*>(&t);
}

#define MMA_F16(d, a0, a1, a2, a3, b0, b1) \
    asm volatile( \
        "mma.sync.aligned.m16n8k16.row.col.f32.f16.f16.f32 " \
        "{%0,%1,%2,%3}, {%4,%5,%6,%7}, {%8,%9}, {%0,%1,%2,%3};" \
        : "+f"((d)[0]), "+f"((d)[1]), "+f"((d)[2]), "+f"((d)[3]) \
        : "r"(a0), "r"(a1), "r"(a2), "r"(a3), "r"(b0), "r"(b1))

// ---------------- fused prep: weight transpose (4x) + src/tgt fp16 convert --
__global__ void __launch_bounds__(256) prep_kernel(
    const float* __restrict__ W0, const float* __restrict__ W1,
    const float* __restrict__ W2, const float* __restrict__ W3,
    __half* __restrict__ wt,
    const float* __restrict__ S, const float* __restrict__ T,
    __half* __restrict__ sh, __half* __restrict__ th)
{
    const int bid = blockIdx.x;
    const int tid = threadIdx.x;
    if (bid < 1024) {
        __shared__ float t[32][33];
        const int w   = bid >> 8;
        const int rem = bid & 255;
        const int kt  = (rem & 15) * 32;
        const int nt  = (rem >> 4) * 32;
        const float* W = (w == 0) ? W0 : (w == 1) ? W1 : (w == 2) ? W2 : W3;
        const size_t wo = (size_t)w * CC * CC;
        const int tx = tid & 31, ty = tid >> 5;   // (32, 8)
        #pragma unroll
        for (int i = 0; i < 4; ++i)
            t[ty + i * 8][tx] = W[(size_t)(kt + ty + i * 8) * CC + nt + tx];
        __syncthreads();
        #pragma unroll
        for (int i = 0; i < 4; ++i) {
            float x = t[tx][ty + i * 8];
            wt[wo + (size_t)(nt + ty + i * 8) * CC + kt + tx] = __float2half_rn(x);
        }
    } else {
        const int cb = bid - 1024;                // 0..8191
        const bool is_t = cb >= 4096;
        const float* X = is_t ? T : S;
        __half* o = is_t ? th : sh;
        const int i = (is_t ? cb - 4096 : cb) * 256 + tid;
        const float4 x = reinterpret_cast<const float4*>(X)[i];
        reinterpret_cast<uint2*>(o)[i] =
            make_uint2(pack2h(__float2half_rn(x.x), __float2half_rn(x.y)),
                       pack2h(__float2half_rn(x.z), __float2half_rn(x.w)));
    }
}

// ---------------- fp16 single-term mma GEMM body (3-stage, BK=64) ----------
#define ROWB 144                        // 128B data + 16B pad
#define REG_SZ (128 * ROWB)             // 18432 per region (128 rows)
#define STG_SZ (2 * REG_SZ)             // [A | B] = 36864
#define OFF_B  REG_SZ
#define SM_TOT (3 * STG_SZ)             // 110592

template <typename OutT>
__device__ __forceinline__ void store2(OutT* p, float a, float b);
template <> __device__ __forceinline__ void store2<float>(float* p, float a, float b) {
    *reinterpret_cast<float2*>(p) = make_float2(a, b);
}
template <> __device__ __forceinline__ void store2<__half>(__half* p, float a, float b) {
    *reinterpret_cast<__half2*>(p) = __floats2half2_rn(a, b);
}

template <typename OutT>
__device__ __forceinline__ void gemm_body(
    uint32_t sb, const __half* __restrict__ A, const __half* __restrict__ Wt,
    const float* __restrict__ bias, OutT* __restrict__ C,
    int bm, int bn)
{
    const int tid  = threadIdx.x;
    const int wid  = tid >> 5;
    const int lane = tid & 31;
    const int wm   = wid & 1;
    const int wn   = wid >> 1;

    const int lr = tid >> 3;            // 0..31
    const int lq = tid & 7;             // 16B chunk

    float acc[4][4][4];
    #pragma unroll
    for (int a = 0; a < 4; ++a)
        #pragma unroll
        for (int b = 0; b < 4; ++b)
            #pragma unroll
            for (int c = 0; c < 4; ++c) acc[a][b][c] = 0.f;

    auto load_stage = [&](int s, int kt) {
        const int kb = kt * 64;
        const uint32_t base = (uint32_t)(s * STG_SZ);
        #pragma unroll
        for (int i = 0; i < 4; ++i) {
            const int row = i * 32 + lr;
            const uint32_t so = base + (uint32_t)(row * ROWB + lq * 16);
            cp16(sb + so, A + (size_t)(bm + row) * CC + kb + lq * 8);
            cp16(sb + OFF_B + so, Wt + (size_t)(bn + row) * CC + kb + lq * 8);
        }
    };

    load_stage(0, 0);
    CP_COMMIT();
    load_stage(1, 1);
    CP_COMMIT();

    const int sub16 = lane & 15;
    const int ahalf = lane >> 4;
    const int bn8   = lane & 7;
    const int bk16  = (lane >> 3) & 1;

    #pragma unroll 1
    for (int kt = 0; kt < 8; ++kt) {
        const int s = kt % 3;
        if (kt < 7) { CP_WAIT(1); } else { CP_WAIT(0); }
        __syncthreads();
        if (kt + 2 < 8) {
            load_stage((kt + 2) % 3, kt + 2);
            CP_COMMIT();
        }

        const uint32_t aBase = sb + (uint32_t)(s * STG_SZ);
        const uint32_t bBase = aBase + OFF_B;

        #pragma unroll
        for (int s2 = 0; s2 < 4; ++s2) {
            const int kbyte = s2 * 32;

            uint32_t bh[4][2];
            #pragma unroll
            for (int nf = 0; nf < 4; ++nf) {
                const uint32_t brow = (uint32_t)(wn * 32 + nf * 8 + bn8);
                const uint32_t ba = bBase + brow * ROWB + kbyte + bk16 * 16;
                asm volatile(
                    "ldmatrix.sync.aligned.m8n8.x2.shared.b16 {%0,%1}, [%2];"
                    : "=r"(bh[nf][0]), "=r"(bh[nf][1]) : "r"(ba));
            }
            uint32_t ah[4][4];
            #pragma unroll
            for (int mf = 0; mf < 4; ++mf) {
                const uint32_t arow = (uint32_t)(wm * 64 + mf * 16 + sub16);
                const uint32_t aa = aBase + arow * ROWB + kbyte + ahalf * 16;
                asm volatile(
                    "ldmatrix.sync.aligned.m8n8.x4.shared.b16 {%0,%1,%2,%3}, [%4];"
                    : "=r"(ah[mf][0]), "=r"(ah[mf][1]), "=r"(ah[mf][2]), "=r"(ah[mf][3])
                    : "r"(aa));
            }

            #pragma unroll
            for (int mf = 0; mf < 4; ++mf)
                #pragma unroll
                for (int nf = 0; nf < 4; ++nf)
                    MMA_F16(acc[mf][nf], ah[mf][0], ah[mf][1], ah[mf][2], ah[mf][3],
                            bh[nf][0], bh[nf][1]);
        }
    }

    const int g = lane >> 2;
    const int t = lane & 3;
    #pragma unroll
    for (int mf = 0; mf < 4; ++mf) {
        const int row = bm + wm * 64 + mf * 16 + g;
        #pragma unroll
        for (int nf = 0; nf < 4; ++nf) {
            const int col = wn * 32 + nf * 8 + 2 * t;       // local col in [0,128)
            const float b0 = __ldg(bias + col);
            const float b1 = __ldg(bias + col + 1);
            float* d = acc[mf][nf];
            store2<OutT>(C + (size_t)row * CC + col, d[0] + b0, d[1] + b1);
            store2<OutT>(C + (size_t)(row + 8) * CC + col, d[2] + b0, d[3] + b1);
        }
    }
}

// standard single-output GEMM (used for the O projection, float out)
template <typename OutT>
__global__ void __launch_bounds__(256, 2) mma_gemm_bias(
    const __half* __restrict__ A, const __half* __restrict__ Wt,
    const float* __restrict__ bias, OutT* __restrict__ C)
{
    extern __shared__ char sm[];
    const uint32_t sb = smem_to_u32(sm);
    const int bm = blockIdx.y * 128;
    const int bn = blockIdx.x * 128;
    gemm_body<OutT>(sb, A, Wt, bias + bn, C + bn, bm, bn);
}

// fused Q+K+V GEMM: blockIdx.x in [0,12); w = x>>2 selects projection
__global__ void __launch_bounds__(256, 2) mma_gemm_bias_qkv(
    const __half* __restrict__ Sh, const __half* __restrict__ Th,
    const __half* __restrict__ Wt,   // 3 weights, stride CC*CC
    const float* __restrict__ bq, const float* __restrict__ bk,
    const float* __restrict__ bv,
    __half* __restrict__ Cq, __half* __restrict__ Ck, __half* __restrict__ Cv)
{
    extern __shared__ char sm[];
    const uint32_t sb = smem_to_u32(sm);
    const int bm = blockIdx.y * 128;
    const int w  = blockIdx.x >> 2;       // 0=Q, 1=K, 2=V
    const int bn = (blockIdx.x & 3) * 128;
    const __half* A = (w == 0) ? Sh : Th;
    const __half* W = Wt + (size_t)w * CC * CC;
    const float*  b = (w == 0) ? bq : (w == 1) ? bk : bv;
    __half*       C = (w == 0) ? Cq : (w == 1) ? Ck : Cv;
    gemm_body<__half>(sb, A, W, b + bn, C + bn, bm, bn);
}

// ---------------- gather attention: fp16 Q/K/V, one warp per (b,q) ----------
__global__ void __launch_bounds__(256, 6) attn_kernel(
    const __half* __restrict__ q, const __half* __restrict__ k,
    const __half* __restrict__ v, const int* __restrict__ indices,
    const float* __restrict__ weights, __half* __restrict__ oh)
{
    __shared__ float slog[8 * 8 * 33];
    const int wid  = threadIdx.x >> 5;
    const int lane = threadIdx.x & 31;
    const int bq   = blockIdx.x * 8 + wid;
    const int b    = bq >> 12;
    float* sl = slog + wid * (8 * 33);

    const __half* kb = k + (size_t)b * NTGT * CC;
    const __half* vb = v + (size_t)b * NTGT * CC;

    const int idxl = indices[(size_t)bq * KNN + lane];

    float qf[2][8];
    {
        const uint4* qrow = reinterpret_cast<const uint4*>(q + (size_t)bq * CC);
        #pragma unroll
        for (int i = 0; i < 2; ++i) {
            const uint4 qq = qrow[i * 32 + lane];
            const __half2* qh2 = reinterpret_cast<const __half2*>(&qq);
            #pragma unroll
            for (int h2 = 0; h2 < 4; ++h2) {
                const float2 f = __half22float2(qh2[h2]);
                qf[i][2 * h2]     = f.x;
                qf[i][2 * h2 + 1] = f.y;
            }
        }
    }

    #pragma unroll 4
    for (int j = 0; j < KNN; ++j) {
        const int ij = __shfl_sync(0xffffffffu, idxl, j);
        const uint4* krow = reinterpret_cast<const uint4*>(kb + (size_t)ij * CC);
        float part[2];
        #pragma unroll
        for (int i = 0; i < 2; ++i) {
            const uint4 kk = krow[i * 32 + lane];
            const __half2* kh = reinterpret_cast<const __half2*>(&kk);
            float p = 0.f;
            #pragma unroll
            for (int h2 = 0; h2 < 4; ++h2) {
                const float2 kf = __half22float2(kh[h2]);
                p = fmaf(qf[i][2 * h2], kf.x, p);
                p = fmaf(qf[i][2 * h2 + 1], kf.y, p);
            }
            part[i] = p;
        }
        #pragma unroll
        for (int off = 4; off >= 1; off >>= 1) {
            part[0] += __shfl_xor_sync(0xffffffffu, part[0], off);
            part[1] += __shfl_xor_sync(0xffffffffu, part[1], off);
        }
        if ((lane & 7) == 0) {
            sl[(0 * 4 + (lane >> 3)) * 33 + j] = part[0];
            sl[(1 * 4 + (lane >> 3)) * 33 + j] = part[1];
        }
    }
    __syncwarp();

    {
        const int h  = lane >> 2;
        const int j0 = lane & 3;
        float vals[8];
        #pragma unroll
        for (int t = 0; t < 8; ++t) {
            const int j = j0 + 4 * t;
            vals[t] = sl[h * 33 + j] * SCALE + weights[(size_t)bq * KNN + j];
        }
        float m = vals[0];
        #pragma unroll
        for (int t = 1; t < 8; ++t) m = fmaxf(m, vals[t]);
        m = fmaxf(m, __shfl_xor_sync(0xffffffffu, m, 1));
        m = fmaxf(m, __shfl_xor_sync(0xffffffffu, m, 2));
        float s = 0.f;
        #pragma unroll
        for (int t = 0; t < 8; ++t) { vals[t] = __expf(vals[t] - m); s += vals[t]; }
        s += __shfl_xor_sync(0xffffffffu, s, 1);
        s += __shfl_xor_sync(0xffffffffu, s, 2);
        const float inv = 1.f / s;
        #pragma unroll
        for (int t = 0; t < 8; ++t) sl[h * 33 + j0 + 4 * t] = vals[t] * inv;
    }
    __syncwarp();

    float acc[2][8];
    #pragma unroll
    for (int i = 0; i < 2; ++i)
        #pragma unroll
        for (int d = 0; d < 8; ++d) acc[i][d] = 0.f;

    const int hsub = lane >> 3;
    #pragma unroll 4
    for (int j = 0; j < KNN; ++j) {
        const int ij = __shfl_sync(0xffffffffu, idxl, j);
        const uint4* vrow = reinterpret_cast<const uint4*>(vb + (size_t)ij * CC);
        #pragma unroll
        for (int i = 0; i < 2; ++i) {
            const float pj = sl[(i * 4 + hsub) * 33 + j];
            const uint4 vv = vrow[i * 32 + lane];
            const __half2* vh = reinterpret_cast<const __half2*>(&vv);
            #pragma unroll
            for (int h2 = 0; h2 < 4; ++h2) {
                const float2 vf = __half22float2(vh[h2]);
                acc[i][2 * h2]     = fmaf(pj, vf.x, acc[i][2 * h2]);
                acc[i][2 * h2 + 1] = fmaf(pj, vf.y, acc[i][2 * h2 + 1]);
            }
        }
    }

    #pragma unroll
    for (int i = 0; i < 2; ++i) {
        const size_t d = (size_t)bq * CC + i * 256 + lane * 8;
        uint32_t hw[4];
        #pragma unroll
        for (int p = 0; p < 4; ++p)
            hw[p] = pack2h(__float2half_rn(acc[i][2 * p]),
                           __float2half_rn(acc[i][2 * p + 1]));
        *reinterpret_cast<uint4*>(oh + d) = make_uint4(hw[0], hw[1], hw[2], hw[3]);
    }
}

// ---------------- launch ----------------------------------------------------
extern "C" void kernel_launch(void* const* d_in, const int* in_sizes, int n_in,
                              void* d_out, int out_size)
{
    const float* src = (const float*)d_in[0];
    const float* tgt = (const float*)d_in[1];
    const int*   idx = (const int*)d_in[2];
    const float* wts = (const float*)d_in[3];
    const float* Wq  = (const float*)d_in[4];
    const float* bq  = (const float*)d_in[5];
    const float* Wk  = (const float*)d_in[6];
    const float* bk  = (const float*)d_in[7];
    const float* Wv  = (const float*)d_in[8];
    const float* bv  = (const float*)d_in[9];
    const float* Wo  = (const float*)d_in[10];
    const float* bo  = (const float*)d_in[11];
    float*       out = (float*)d_out;

    void *pqh, *pkh, *pvh, *psh, *pth, *poh, *pwt;
    cudaGetSymbolAddress(&pqh, g_qh);
    cudaGetSymbolAddress(&pkh, g_kh);
    cudaGetSymbolAddress(&pvh, g_vh);
    cudaGetSymbolAddress(&psh, g_Sh);
    cudaGetSymbolAddress(&pth, g_Th);
    cudaGetSymbolAddress(&poh, g_Oh);
    cudaGetSymbolAddress(&pwt, g_Wt);
    __half* gqh = (__half*)pqh;
    __half* gkh = (__half*)pkh;
    __half* gvh = (__half*)pvh;
    __half* sh  = (__half*)psh;
    __half* th  = (__half*)pth;
    __half* oh  = (__half*)poh;
    __half* wt  = (__half*)pwt;

    static bool attr_set = false;
    if (!attr_set) {
        cudaFuncSetAttribute(mma_gemm_bias<float>,
                             cudaFuncAttributeMaxDynamicSharedMemorySize, SM_TOT);
        cudaFuncSetAttribute(mma_gemm_bias_qkv,
                             cudaFuncAttributeMaxDynamicSharedMemorySize, SM_TOT);
        attr_set = true;
    }

    const size_t WS = (size_t)CC * CC;

    // fused prep: 1024 transpose blocks + 8192 convert blocks
    prep_kernel<<<9216, 256>>>(Wq, Wk, Wv, Wo, wt, src, tgt, sh, th);

    dim3 qkvgrid(3 * CC / 128, MROWS / 128);   // (12, 64) = 768 CTAs
    mma_gemm_bias_qkv<<<qkvgrid, 256, SM_TOT>>>(sh, th, wt,
                                                bq, bk, bv, gqh, gkh, gvh);

    attn_kernel<<<BB * HW / 8, 256>>>(gqh, gkh, gvh, idx, wts, oh);

    dim3 ggrid(CC / 128, MROWS / 128);         // (4, 64)
    mma_gemm_bias<float><<<ggrid, 256, SM_TOT>>>(oh, wt + 3 * WS, bo, out);
}